// round 9
// baseline (speedup 1.0000x reference)
#include <cuda_runtime.h>
#include <cuda_bf16.h>
#include <math.h>
#include <stdint.h>

#define B_    16
#define HH_   48
#define WW_   48
#define N_    2304
#define C_    384
#define C2_   768
#define NH_   8
#define DD_   48
#define ROWS_ 36864

typedef __nv_bfloat16 bf16;

// ---------------- device scratch ----------------
__device__ bf16  g_xnb [(size_t)ROWS_ * C_];
__device__ bf16  g_qkvT[(size_t)3 * B_ * C_ * N_];   // [s][b][cc][n] bf16
__device__ float g_attn[B_ * NH_ * DD_ * DD_];
__device__ bf16  g_oncb[(size_t)ROWS_ * C_];
__device__ float g_x1  [(size_t)ROWS_ * C_];
__device__ bf16  g_hidb[(size_t)ROWS_ * C2_];
__device__ float g_x2  [(size_t)ROWS_ * C_];
__device__ bf16  g_c1b [(size_t)ROWS_ * C_];
__device__ bf16  g_wqkvb[3 * C_ * C_];
__device__ bf16  g_wprojb[C_ * C_];
__device__ bf16  g_w1b [C2_ * C_];
__device__ bf16  g_w2b [C_ * C2_];
__device__ bf16  g_wt1b[9 * C_ * C_];
__device__ bf16  g_wt2b[9 * C_ * C_];

__device__ __forceinline__ float gelu_f(float v) {
    return 0.5f * v * (1.0f + erff(v * 0.70710678118654752440f));
}

__device__ __forceinline__ uint32_t smem_u32(const void* p) {
    uint32_t r;
    asm("{ .reg .u64 t; cvta.to.shared.u64 t, %1; cvt.u32.u64 %0, t; }" : "=r"(r) : "l"(p));
    return r;
}
#define SW128(o) ((o) ^ (((o) >> 3) & 0x70))

__device__ __forceinline__ void ldm4(uint32_t (&d)[4], uint32_t addr) {
    asm volatile("ldmatrix.sync.aligned.m8n8.x4.shared.b16 {%0,%1,%2,%3}, [%4];"
                 : "=r"(d[0]), "=r"(d[1]), "=r"(d[2]), "=r"(d[3]) : "r"(addr));
}
__device__ __forceinline__ void mma16816(float (&c)[4], const uint32_t (&a)[4],
                                         uint32_t b0, uint32_t b1) {
    asm volatile("mma.sync.aligned.m16n8k16.row.col.f32.bf16.bf16.f32 "
                 "{%0,%1,%2,%3}, {%4,%5,%6,%7}, {%8,%9}, {%0,%1,%2,%3};"
                 : "+f"(c[0]), "+f"(c[1]), "+f"(c[2]), "+f"(c[3])
                 : "r"(a[0]), "r"(a[1]), "r"(a[2]), "r"(a[3]), "r"(b0), "r"(b1));
}
__device__ __forceinline__ void cpa16(uint32_t dst, const void* src) {
    asm volatile("cp.async.cg.shared.global [%0], [%1], 16;" :: "r"(dst), "l"(src));
}
__device__ __forceinline__ void cpa16z(uint32_t dst, const void* src, bool ok) {
    int sz = ok ? 16 : 0;
    asm volatile("cp.async.cg.shared.global [%0], [%1], 16, %2;" :: "r"(dst), "l"(src), "r"(sz));
}
#define CP_COMMIT() asm volatile("cp.async.commit_group;" ::: "memory")

// smem: 4 stages x (A 16K + B 8K) = 96KB
#define STAGES 4
#define STAGE_BYTES 24576
#define SMEM_BYTES (STAGES * STAGE_BYTES)

// ---------------- MMA for one K=64 stage: warp tile 32x32 (8 warps over 128x64) ----------------
__device__ __forceinline__ void stage_mma(uint32_t sbase, uint32_t Aoff, uint32_t Boff,
                                          int am_base, int bn_base, int lane,
                                          float (&acc)[2][4][4])
{
    const int arow = ((lane >> 3) & 1) * 8 + (lane & 7);
    const int akb  = ((lane >> 4) & 1) * 16;
    const int brow = ((lane >> 4) & 1) * 8 + (lane & 7);
    const int bkb  = ((lane >> 3) & 1) * 16;
#pragma unroll
    for (int kk = 0; kk < 64; kk += 16) {
        uint32_t a0[4], a1[4], b0[4], b1[4];
        ldm4(a0, sbase + Aoff + SW128((am_base + arow) * 128 + kk * 2 + akb));
        ldm4(a1, sbase + Aoff + SW128((am_base + 16 + arow) * 128 + kk * 2 + akb));
        ldm4(b0, sbase + Boff + SW128((bn_base + brow) * 128 + kk * 2 + bkb));
        ldm4(b1, sbase + Boff + SW128((bn_base + 16 + brow) * 128 + kk * 2 + bkb));
        mma16816(acc[0][0], a0, b0[0], b0[1]);
        mma16816(acc[0][1], a0, b0[2], b0[3]);
        mma16816(acc[0][2], a0, b1[0], b1[1]);
        mma16816(acc[0][3], a0, b1[2], b1[3]);
        mma16816(acc[1][0], a1, b0[0], b0[1]);
        mma16816(acc[1][1], a1, b0[2], b0[3]);
        mma16816(acc[1][2], a1, b1[0], b1[1]);
        mma16816(acc[1][3], a1, b1[2], b1[3]);
    }
}

// ---------------- epilogues ----------------
// EPI 0: qkv transposed scatter -> bf16 (via smem). 1: out=e4+e5*acc. 2: gelu(bn)->bf16. 3: e4+e5*bn.
template <int EPI, typename OutT>
__device__ __forceinline__ void epi_frag(float (&acc)[2][4][4], char* smem,
                                         int m0, int n0, int wm, int wn, int lane, int t, int ldo,
                                         const float* __restrict__ e0, const float* __restrict__ e1,
                                         const float* __restrict__ e2, const float* __restrict__ e3,
                                         const float* __restrict__ e4, const float* __restrict__ e5,
                                         OutT* __restrict__ out)
{
    const int rIn = lane >> 2, cpair = (lane & 3) * 2;
    if (EPI == 0) {
        float* smf = (float*)smem;     // [64 n][132 m-pad]
        __syncthreads();
#pragma unroll
        for (int ni = 0; ni < 4; ni++) {
            const int cl = wn * 32 + ni * 8 + cpair;
#pragma unroll
            for (int mi = 0; mi < 2; mi++) {
#pragma unroll
                for (int h = 0; h < 2; h++) {
                    const int rl = wm * 32 + mi * 16 + rIn + h * 8;
                    smf[(cl + 0) * 132 + rl] = acc[mi][ni][2 * h + 0];
                    smf[(cl + 1) * 132 + rl] = acc[mi][ni][2 * h + 1];
                }
            }
        }
        __syncthreads();
        const int b = m0 / N_;
        const int nrow0 = (m0 - b * N_);
        const int rown = t & 63, seg = t >> 6;
        const int rr = n0 + rown;
        const int s = rr / C_, cc = rr - s * C_;
        bf16* dst = (bf16*)out + ((size_t)(s * B_ + b) * C_ + cc) * (size_t)N_ + nrow0 + seg * 32;
        const float* src = smf + rown * 132 + seg * 32;
#pragma unroll
        for (int i = 0; i < 8; i++) {
            float4 v = *(const float4*)(src + i * 4);
            __nv_bfloat162 p0 = __floats2bfloat162_rn(v.x, v.y);
            __nv_bfloat162 p1 = __floats2bfloat162_rn(v.z, v.w);
            uint2 u;
            u.x = *(uint32_t*)&p0;
            u.y = *(uint32_t*)&p1;
            *(uint2*)(dst + i * 4) = u;
        }
        return;
    }
#pragma unroll
    for (int ni = 0; ni < 4; ni++) {
        const int col = n0 + wn * 32 + ni * 8 + cpair;
        float s0 = 1.f, s1 = 1.f, bi0 = 0.f, bi1 = 0.f, g0 = 0.f, g1 = 0.f;
        if (EPI == 2 || EPI == 3) {
            s0 = e0[col + 0] * rsqrtf(e3[col + 0] + 1e-5f);
            s1 = e0[col + 1] * rsqrtf(e3[col + 1] + 1e-5f);
            bi0 = e1[col + 0] - e2[col + 0] * s0;
            bi1 = e1[col + 1] - e2[col + 1] * s1;
        }
        if (EPI == 1 || EPI == 3) { g0 = e5[col]; g1 = e5[col + 1]; }
#pragma unroll
        for (int mi = 0; mi < 2; mi++) {
#pragma unroll
            for (int h = 0; h < 2; h++) {
                const int row = m0 + wm * 32 + mi * 16 + rIn + h * 8;
                float a0 = acc[mi][ni][2 * h + 0];
                float a1 = acc[mi][ni][2 * h + 1];
                if (EPI == 2 || EPI == 3) { a0 = a0 * s0 + bi0; a1 = a1 * s1 + bi1; }
                if (EPI == 2) { a0 = gelu_f(a0); a1 = gelu_f(a1); }
                const size_t off = (size_t)row * ldo + col;
                if (EPI == 1 || EPI == 3) {
                    float2 xr = *(const float2*)(e4 + off);
                    a0 = xr.x + g0 * a0; a1 = xr.y + g1 * a1;
                }
                if (sizeof(OutT) == 2) {
                    __nv_bfloat162 p = __floats2bfloat162_rn(a0, a1);
                    *(uint32_t*)((bf16*)out + off) = *(uint32_t*)&p;
                } else {
                    *(float2*)((float*)out + off) = make_float2(a0, a1);
                }
            }
        }
    }
}

// ---------------- dense NT GEMM: D[128x64] = A[128xK] * Bw[64xK]^T, 4-stage cp.async ----------------
template <int EPI, typename OutT>
__global__ void __launch_bounds__(256, 2) tc_gemm(
    const bf16* __restrict__ A, const bf16* __restrict__ Bw, int K, int ldo,
    const float* __restrict__ e0, const float* __restrict__ e1,
    const float* __restrict__ e2, const float* __restrict__ e3,
    const float* __restrict__ e4, const float* __restrict__ e5,
    OutT* __restrict__ out)
{
    extern __shared__ char smem[];
    const int t = threadIdx.x, wid = t >> 5, lane = t & 31;
    const int m0 = blockIdx.x * 128, n0 = blockIdx.y * 64;
    const int wm = wid & 3, wn = wid >> 2;
    const uint32_t sbase = smem_u32(smem);
    const int q = t & 7, r0 = t >> 3;
    const int nc = K >> 6;

    float acc[2][4][4];
#pragma unroll
    for (int i = 0; i < 2; i++)
#pragma unroll
        for (int j = 0; j < 4; j++)
#pragma unroll
            for (int k = 0; k < 4; k++) acc[i][j][k] = 0.f;

    const char* Abase = (const char*)(A + (size_t)m0 * K);
    const char* Bbase = (const char*)(Bw + (size_t)n0 * K);
    const size_t rs = (size_t)K * 2;
    uint32_t sw[4];
#pragma unroll
    for (int it = 0; it < 4; it++) sw[it] = SW128((r0 + it * 32) * 128 + q * 16);

    auto issue = [&](int c) {
        const uint32_t so = sbase + (uint32_t)(c % STAGES) * STAGE_BYTES;
        const size_t ko = (size_t)c * 128 + q * 16;
#pragma unroll
        for (int it = 0; it < 4; it++)
            cpa16(so + sw[it], Abase + (size_t)(r0 + it * 32) * rs + ko);
#pragma unroll
        for (int it = 0; it < 2; it++)
            cpa16(so + 16384 + sw[it], Bbase + (size_t)(r0 + it * 32) * rs + ko);
        CP_COMMIT();
    };

    for (int s = 0; s < STAGES - 1 && s < nc; s++) issue(s);
    for (int c = 0; c < nc; c++) {
        if (c + STAGES - 1 < nc) {
            asm volatile("cp.async.wait_group %0;" :: "n"(STAGES - 2) : "memory");
        } else {
            asm volatile("cp.async.wait_group 0;" ::: "memory");
        }
        __syncthreads();
        const uint32_t so = (uint32_t)(c % STAGES) * STAGE_BYTES;
        stage_mma(sbase, so, so + 16384, wm * 32, wn * 32, lane, acc);
        if (c + STAGES - 1 < nc) issue(c + STAGES - 1);
    }
    epi_frag<EPI, OutT>(acc, smem, m0, n0, wm, wn, lane, t, ldo, e0, e1, e2, e3, e4, e5, out);
}

// ---------------- 3x3 conv as 9-tap K-accumulated GEMM, 4-stage cp.async ----------------
template <int EPI, typename OutT>
__global__ void __launch_bounds__(256, 2) tc_conv(
    const bf16* __restrict__ A, const bf16* __restrict__ Wt,
    const float* __restrict__ e0, const float* __restrict__ e1,
    const float* __restrict__ e2, const float* __restrict__ e3,
    const float* __restrict__ e4, const float* __restrict__ e5,
    OutT* __restrict__ out)
{
    extern __shared__ char smem[];
    const int t = threadIdx.x, wid = t >> 5, lane = t & 31;
    const int m0 = blockIdx.x * 128, n0 = blockIdx.y * 64;
    const int wm = wid & 3, wn = wid >> 2;
    const uint32_t sbase = smem_u32(smem);
    const int q = t & 7, r0 = t >> 3;

    const int m0p = m0 % N_;
    int hh[4], ww[4];
#pragma unroll
    for (int it = 0; it < 4; it++) {
        int p = m0p + r0 + it * 32;
        hh[it] = p / WW_;
        ww[it] = p - hh[it] * WW_;
    }
    uint32_t sw[4];
#pragma unroll
    for (int it = 0; it < 4; it++) sw[it] = SW128((r0 + it * 32) * 128 + q * 16);

    float acc[2][4][4];
#pragma unroll
    for (int i = 0; i < 2; i++)
#pragma unroll
        for (int j = 0; j < 4; j++)
#pragma unroll
            for (int k = 0; k < 4; k++) acc[i][j][k] = 0.f;

    auto issue = [&](int c) {
        const int tap = c / 6, kc = c - tap * 6;
        const int dy = tap / 3 - 1, dx = tap % 3 - 1;
        const uint32_t so = sbase + (uint32_t)(c % STAGES) * STAGE_BYTES;
        const bf16* Atap = A + (size_t)(m0 + dy * WW_ + dx) * C_ + kc * 64;
        const bf16* Wtap = Wt + (size_t)tap * C_ * C_ + (size_t)n0 * C_ + kc * 64;
#pragma unroll
        for (int it = 0; it < 4; it++) {
            bool ok = ((unsigned)(hh[it] + dy) < (unsigned)HH_) &&
                      ((unsigned)(ww[it] + dx) < (unsigned)WW_);
            cpa16z(so + sw[it], (const char*)(Atap + (size_t)(r0 + it * 32) * C_) + q * 16, ok);
        }
#pragma unroll
        for (int it = 0; it < 2; it++)
            cpa16(so + 16384 + sw[it], (const char*)(Wtap + (size_t)(r0 + it * 32) * C_) + q * 16);
        CP_COMMIT();
    };

    const int nc = 54;
    for (int s = 0; s < STAGES - 1; s++) issue(s);
    for (int c = 0; c < nc; c++) {
        if (c + STAGES - 1 < nc) {
            asm volatile("cp.async.wait_group %0;" :: "n"(STAGES - 2) : "memory");
        } else {
            asm volatile("cp.async.wait_group 0;" ::: "memory");
        }
        __syncthreads();
        const uint32_t so = (uint32_t)(c % STAGES) * STAGE_BYTES;
        stage_mma(sbase, so, so + 16384, wm * 32, wn * 32, lane, acc);
        if (c + STAGES - 1 < nc) issue(c + STAGES - 1);
    }
    epi_frag<EPI, OutT>(acc, smem, m0, n0, wm, wn, lane, t, C_, e0, e1, e2, e3, e4, e5, out);
}

// ---------------- LayerNorm -> bf16 ----------------
__global__ void ln_kernel(const float* __restrict__ in, const float* __restrict__ g,
                          const float* __restrict__ b, bf16* __restrict__ outp)
{
    const int r = blockIdx.x;
    const int t = threadIdx.x;
    const float* row = in + (size_t)r * C_;
    float v0 = row[t], v1 = row[t + 128], v2 = row[t + 256];
    float s = v0 + v1 + v2;
    float ss = v0 * v0 + v1 * v1 + v2 * v2;
    for (int o = 16; o; o >>= 1) {
        s  += __shfl_down_sync(0xffffffffu, s,  o);
        ss += __shfl_down_sync(0xffffffffu, ss, o);
    }
    __shared__ float sh[8];
    if ((t & 31) == 0) { sh[t >> 5] = s; sh[4 + (t >> 5)] = ss; }
    __syncthreads();
    if (t == 0) {
        float S  = sh[0] + sh[1] + sh[2] + sh[3];
        float SS = sh[4] + sh[5] + sh[6] + sh[7];
        float mean = S * (1.0f / C_);
        float var  = SS * (1.0f / C_) - mean * mean;
        sh[0] = mean;
        sh[1] = rsqrtf(var + 1e-5f);
    }
    __syncthreads();
    float mean = sh[0], rstd = sh[1];
    bf16* orow = outp + (size_t)r * C_;
    orow[t]       = __float2bfloat16_rn((v0 - mean) * rstd * g[t]       + b[t]);
    orow[t + 128] = __float2bfloat16_rn((v1 - mean) * rstd * g[t + 128] + b[t + 128]);
    orow[t + 256] = __float2bfloat16_rn((v2 - mean) * rstd * g[t + 256] + b[t + 256]);
}

// ---------------- conversions ----------------
__global__ void f2bf(const float* __restrict__ in, bf16* __restrict__ outp, int n)
{
    int i = blockIdx.x * 256 + threadIdx.x;
    if (i < n) outp[i] = __float2bfloat16_rn(in[i]);
}
__global__ void wtrans_bf(const float* __restrict__ w, bf16* __restrict__ wt)
{
    int i = blockIdx.x * 256 + threadIdx.x;
    if (i >= 9 * C_ * C_) return;
    int tap = i / (C_ * C_);
    int rem = i - tap * (C_ * C_);
    int o = rem / C_, ci = rem - o * C_;
    wt[i] = __float2bfloat16_rn(w[(size_t)(o * C_ + ci) * 9 + tap]);
}

// ---------------- fused q/k norm + S + softmax: one block per (b,h) ----------------
__global__ void attn_qk(const float* __restrict__ temp)
{
    const int bh = blockIdx.x;
    const int b = bh >> 3, h = bh & 7;
    __shared__ float qs[DD_ * 65];
    __shared__ float ks[DD_ * 65];
    __shared__ float qss_s[DD_];
    __shared__ float kss_s[DD_];
    const int t = threadIdx.x;
    const bf16* qbase = g_qkvT + ((size_t)(b)      * C_ + h * DD_) * N_;
    const bf16* kbase = g_qkvT + ((size_t)(B_ + b) * C_ + h * DD_) * N_;
    float acc[3][3] = {};
    float qss[3] = {0.f, 0.f, 0.f}, kss[3] = {0.f, 0.f, 0.f};
    const int ty = t >> 4, tx = t & 15;
    const int d0 = ty * 3, e0i = tx * 3;
    for (int n0 = 0; n0 < N_; n0 += 64) {
        __syncthreads();
        for (int idx = t; idx < DD_ * 32; idx += 256) {
            int d = idx >> 5, nn2 = (idx & 31) * 2;
            float2 qf = __bfloat1622float2(*(const __nv_bfloat162*)(qbase + (size_t)d * N_ + n0 + nn2));
            float2 kf = __bfloat1622float2(*(const __nv_bfloat162*)(kbase + (size_t)d * N_ + n0 + nn2));
            qs[d * 65 + nn2] = qf.x; qs[d * 65 + nn2 + 1] = qf.y;
            ks[d * 65 + nn2] = kf.x; ks[d * 65 + nn2 + 1] = kf.y;
        }
        __syncthreads();
#pragma unroll 4
        for (int nn = 0; nn < 64; nn++) {
            float q0 = qs[d0 * 65 + nn], q1 = qs[(d0 + 1) * 65 + nn], q2 = qs[(d0 + 2) * 65 + nn];
            float k0 = ks[e0i * 65 + nn], k1 = ks[(e0i + 1) * 65 + nn], k2 = ks[(e0i + 2) * 65 + nn];
            acc[0][0] += q0 * k0; acc[0][1] += q0 * k1; acc[0][2] += q0 * k2;
            acc[1][0] += q1 * k0; acc[1][1] += q1 * k1; acc[1][2] += q1 * k2;
            acc[2][0] += q2 * k0; acc[2][1] += q2 * k1; acc[2][2] += q2 * k2;
            if (tx == 0) { qss[0] += q0 * q0; qss[1] += q1 * q1; qss[2] += q2 * q2; }
            if (ty == 0) { kss[0] += k0 * k0; kss[1] += k1 * k1; kss[2] += k2 * k2; }
        }
    }
    if (tx == 0) {
#pragma unroll
        for (int i = 0; i < 3; i++) qss_s[d0 + i] = qss[i];
    }
    if (ty == 0) {
#pragma unroll
        for (int j = 0; j < 3; j++) kss_s[e0i + j] = kss[j];
    }
    __syncthreads();
    const float tp = temp[h];
    float rq[3], rk[3];
#pragma unroll
    for (int i = 0; i < 3; i++) rq[i] = 1.0f / fmaxf(sqrtf(qss_s[d0 + i]), 1e-12f);
#pragma unroll
    for (int j = 0; j < 3; j++) rk[j] = 1.0f / fmaxf(sqrtf(kss_s[e0i + j]), 1e-12f);
    float* S = qs;    // reuse, 48*48 floats
    __syncthreads();
#pragma unroll
    for (int i = 0; i < 3; i++)
#pragma unroll
        for (int j = 0; j < 3; j++)
            S[(d0 + i) * DD_ + e0i + j] = acc[i][j] * rq[i] * rk[j] * tp;
    __syncthreads();
    if (t < DD_) {
        float mx = -1e30f;
#pragma unroll
        for (int j = 0; j < DD_; j++) mx = fmaxf(mx, S[t * DD_ + j]);
        float sum = 0.f;
#pragma unroll
        for (int j = 0; j < DD_; j++) { float e = expf(S[t * DD_ + j] - mx); S[t * DD_ + j] = e; sum += e; }
        float r = 1.0f / sum;
        float* dst = g_attn + (size_t)bh * DD_ * DD_ + t * DD_;
#pragma unroll
        for (int j = 0; j < DD_; j++) dst[j] = S[t * DD_ + j] * r;
    }
}

__global__ void attn_v()
{
    const int nt = blockIdx.x;
    const int bh = blockIdx.y;
    const int b = bh >> 3, h = bh & 7;
    __shared__ float P[DD_ * DD_];
    __shared__ float vs[DD_ * 132];
    const int t = threadIdx.x;
    for (int idx = t; idx < DD_ * DD_; idx += 256) P[idx] = g_attn[(size_t)bh * DD_ * DD_ + idx];
    const bf16* vbase = g_qkvT + ((size_t)(2 * B_ + b) * C_ + h * DD_) * N_ + nt * 128;
    for (int idx = t; idx < DD_ * 64; idx += 256) {
        int e = idx >> 6, nn2 = (idx & 63) * 2;
        float2 vf = __bfloat1622float2(*(const __nv_bfloat162*)(vbase + (size_t)e * N_ + nn2));
        vs[e * 132 + nn2] = vf.x;
        vs[e * 132 + nn2 + 1] = vf.y;
    }
    __syncthreads();
    const int ng = t & 31, dg = t >> 5;
    const int n = ng * 4, dd0 = dg * 6;
    float acc[6][4] = {};
#pragma unroll 4
    for (int e = 0; e < DD_; e++) {
        float4 v4 = *(const float4*)&vs[e * 132 + n];
#pragma unroll
        for (int i = 0; i < 6; i++) {
            float pv = P[(dd0 + i) * DD_ + e];
            acc[i][0] += pv * v4.x; acc[i][1] += pv * v4.y;
            acc[i][2] += pv * v4.z; acc[i][3] += pv * v4.w;
        }
    }
    size_t mbase = ((size_t)b * N_ + nt * 128 + n) * C_ + h * DD_ + dd0;
#pragma unroll
    for (int i = 0; i < 6; i++)
#pragma unroll
        for (int jj = 0; jj < 4; jj++)
            g_oncb[mbase + i + (size_t)jj * C_] = __float2bfloat16_rn(acc[i][jj]);
}

__global__ void tail_kernel(float* o, const int* pH, const int* pW, int extra)
{
    int i = threadIdx.x;
    if (i < extra) {
        float v = 0.f;
        if (i == 0) v = (float)(*pH);
        if (i == 1) v = (float)(*pW);
        o[(size_t)ROWS_ * C_ + i] = v;
    }
}

extern "C" void kernel_launch(void* const* d_in, const int* in_sizes, int n_in,
                              void* d_out, int out_size)
{
    const float* x      = (const float*)d_in[0];
    const float* ln1_g  = (const float*)d_in[1];
    const float* ln1_b  = (const float*)d_in[2];
    const float* w_qkv  = (const float*)d_in[3];
    const float* temp   = (const float*)d_in[4];
    const float* w_proj = (const float*)d_in[5];
    const float* gamma1 = (const float*)d_in[6];
    const float* ln2_g  = (const float*)d_in[7];
    const float* ln2_b  = (const float*)d_in[8];
    const float* mlp_w1 = (const float*)d_in[9];
    const float* bn1_g  = (const float*)d_in[10];
    const float* bn1_b  = (const float*)d_in[11];
    const float* bn1_m  = (const float*)d_in[12];
    const float* bn1_v  = (const float*)d_in[13];
    const float* mlp_w2 = (const float*)d_in[14];
    const float* bn2_g  = (const float*)d_in[15];
    const float* bn2_b  = (const float*)d_in[16];
    const float* bn2_m  = (const float*)d_in[17];
    const float* bn2_v  = (const float*)d_in[18];
    const float* gamma2 = (const float*)d_in[19];
    const float* ln3_g  = (const float*)d_in[20];
    const float* ln3_b  = (const float*)d_in[21];
    const float* pconv1 = (const float*)d_in[22];
    const float* pbn_g  = (const float*)d_in[23];
    const float* pbn_b  = (const float*)d_in[24];
    const float* pbn_m  = (const float*)d_in[25];
    const float* pbn_v  = (const float*)d_in[26];
    const float* pconv2 = (const float*)d_in[27];
    const float* gamma3 = (const float*)d_in[28];
    const int*   pH     = (const int*)d_in[29];
    const int*   pW     = (const int*)d_in[30];
    float* dout = (float*)d_out;

    bf16 *xnb, *qkvT, *oncb, *hidb, *c1b, *wqkvb, *wprojb, *w1b, *w2b, *wt1b, *wt2b;
    float *x1, *x2;
    cudaGetSymbolAddress((void**)&xnb,    g_xnb);
    cudaGetSymbolAddress((void**)&qkvT,   g_qkvT);
    cudaGetSymbolAddress((void**)&oncb,   g_oncb);
    cudaGetSymbolAddress((void**)&x1,     g_x1);
    cudaGetSymbolAddress((void**)&hidb,   g_hidb);
    cudaGetSymbolAddress((void**)&x2,     g_x2);
    cudaGetSymbolAddress((void**)&c1b,    g_c1b);
    cudaGetSymbolAddress((void**)&wqkvb,  g_wqkvb);
    cudaGetSymbolAddress((void**)&wprojb, g_wprojb);
    cudaGetSymbolAddress((void**)&w1b,    g_w1b);
    cudaGetSymbolAddress((void**)&w2b,    g_w2b);
    cudaGetSymbolAddress((void**)&wt1b,   g_wt1b);
    cudaGetSymbolAddress((void**)&wt2b,   g_wt2b);

    cudaFuncSetAttribute((const void*)tc_gemm<0, bf16>,  cudaFuncAttributeMaxDynamicSharedMemorySize, SMEM_BYTES);
    cudaFuncSetAttribute((const void*)tc_gemm<1, float>, cudaFuncAttributeMaxDynamicSharedMemorySize, SMEM_BYTES);
    cudaFuncSetAttribute((const void*)tc_gemm<2, bf16>,  cudaFuncAttributeMaxDynamicSharedMemorySize, SMEM_BYTES);
    cudaFuncSetAttribute((const void*)tc_gemm<3, float>, cudaFuncAttributeMaxDynamicSharedMemorySize, SMEM_BYTES);
    cudaFuncSetAttribute((const void*)tc_conv<2, bf16>,  cudaFuncAttributeMaxDynamicSharedMemorySize, SMEM_BYTES);
    cudaFuncSetAttribute((const void*)tc_conv<1, float>, cudaFuncAttributeMaxDynamicSharedMemorySize, SMEM_BYTES);

    const float* np = nullptr;

    // weight conversions
    f2bf<<<(3 * C_ * C_ + 255) / 256, 256>>>(w_qkv, wqkvb, 3 * C_ * C_);
    f2bf<<<(C_ * C_ + 255) / 256, 256>>>(w_proj, wprojb, C_ * C_);
    f2bf<<<(C2_ * C_ + 255) / 256, 256>>>(mlp_w1, w1b, C2_ * C_);
    f2bf<<<(C_ * C2_ + 255) / 256, 256>>>(mlp_w2, w2b, C_ * C2_);
    wtrans_bf<<<(9 * C_ * C_ + 255) / 256, 256>>>(pconv1, wt1b);
    wtrans_bf<<<(9 * C_ * C_ + 255) / 256, 256>>>(pconv2, wt2b);

    // --- attention block ---
    ln_kernel<<<ROWS_, 128>>>(x, ln1_g, ln1_b, xnb);
    tc_gemm<0, bf16><<<dim3(288, 18), 256, SMEM_BYTES>>>(xnb, wqkvb, C_, 0, np, np, np, np, np, np, qkvT);
    attn_qk<<<B_ * NH_, 256>>>(temp);
    attn_v<<<dim3(18, B_ * NH_), 256>>>();
    tc_gemm<1, float><<<dim3(288, 6), 256, SMEM_BYTES>>>(oncb, wprojb, C_, C_, np, np, np, np, x, gamma1, x1);

    // --- ConvMlp block ---
    ln_kernel<<<ROWS_, 128>>>(x1, ln2_g, ln2_b, xnb);
    tc_gemm<2, bf16><<<dim3(288, 12), 256, SMEM_BYTES>>>(xnb, w1b, C_, C2_, bn1_g, bn1_b, bn1_m, bn1_v, np, np, hidb);
    tc_gemm<3, float><<<dim3(288, 6), 256, SMEM_BYTES>>>(hidb, w2b, C2_, C_, bn2_g, bn2_b, bn2_m, bn2_v, x1, gamma2, x2);

    // --- projection block (3x3 convs) ---
    ln_kernel<<<ROWS_, 128>>>(x2, ln3_g, ln3_b, xnb);
    tc_conv<2, bf16><<<dim3(288, 6), 256, SMEM_BYTES>>>(xnb, wt1b, pbn_g, pbn_b, pbn_m, pbn_v, np, np, c1b);
    tc_conv<1, float><<<dim3(288, 6), 256, SMEM_BYTES>>>(c1b, wt2b, np, np, np, np, x2, gamma3, dout);

    int extra = out_size - (int)((size_t)ROWS_ * C_);
    if (extra > 0) tail_kernel<<<1, 32>>>(dout, pH, pW, extra);
}

// round 11
// speedup vs baseline: 1.5063x; 1.5063x over previous
#include <cuda_runtime.h>
#include <cuda_bf16.h>
#include <math.h>
#include <stdint.h>

#define B_    16
#define HH_   48
#define WW_   48
#define N_    2304
#define C_    384
#define C2_   768
#define NH_   8
#define DD_   48
#define ROWS_ 36864

typedef __nv_bfloat16 bf16;

// ---------------- device scratch ----------------
__device__ bf16  g_xnb [(size_t)ROWS_ * C_];
__device__ bf16  g_qkvT[(size_t)3 * B_ * C_ * N_];   // [s][b][cc][n] bf16
__device__ float g_attn[B_ * NH_ * DD_ * DD_];
__device__ bf16  g_oncb[(size_t)ROWS_ * C_];
__device__ float g_x1  [(size_t)ROWS_ * C_];
__device__ bf16  g_hidb[(size_t)ROWS_ * C2_];
__device__ float g_x2  [(size_t)ROWS_ * C_];
__device__ bf16  g_c1b [(size_t)ROWS_ * C_];
__device__ bf16  g_wqkvb[3 * C_ * C_];
__device__ bf16  g_wprojb[C_ * C_];
__device__ bf16  g_w1b [C2_ * C_];
__device__ bf16  g_w2b [C_ * C2_];
__device__ bf16  g_wt1b[9 * C_ * C_];
__device__ bf16  g_wt2b[9 * C_ * C_];

__device__ __forceinline__ float gelu_f(float v) {
    return 0.5f * v * (1.0f + erff(v * 0.70710678118654752440f));
}

__device__ __forceinline__ uint32_t smem_u32(const void* p) {
    uint32_t r;
    asm("{ .reg .u64 t; cvta.to.shared.u64 t, %1; cvt.u32.u64 %0, t; }" : "=r"(r) : "l"(p));
    return r;
}
#define SW128(o) ((o) ^ (((o) >> 3) & 0x70))

__device__ __forceinline__ void ldm4(uint32_t (&d)[4], uint32_t addr) {
    asm volatile("ldmatrix.sync.aligned.m8n8.x4.shared.b16 {%0,%1,%2,%3}, [%4];"
                 : "=r"(d[0]), "=r"(d[1]), "=r"(d[2]), "=r"(d[3]) : "r"(addr));
}
__device__ __forceinline__ void mma16816(float (&c)[4], const uint32_t (&a)[4],
                                         uint32_t b0, uint32_t b1) {
    asm volatile("mma.sync.aligned.m16n8k16.row.col.f32.bf16.bf16.f32 "
                 "{%0,%1,%2,%3}, {%4,%5,%6,%7}, {%8,%9}, {%0,%1,%2,%3};"
                 : "+f"(c[0]), "+f"(c[1]), "+f"(c[2]), "+f"(c[3])
                 : "r"(a[0]), "r"(a[1]), "r"(a[2]), "r"(a[3]), "r"(b0), "r"(b1));
}
__device__ __forceinline__ void cpa16(uint32_t dst, const void* src) {
    asm volatile("cp.async.cg.shared.global [%0], [%1], 16;" :: "r"(dst), "l"(src));
}
__device__ __forceinline__ void cpa16z(uint32_t dst, const void* src, bool ok) {
    int sz = ok ? 16 : 0;
    asm volatile("cp.async.cg.shared.global [%0], [%1], 16, %2;" :: "r"(dst), "l"(src), "r"(sz));
}
#define CP_COMMIT() asm volatile("cp.async.commit_group;" ::: "memory")

// smem: 3 stages x (A 16K + B 8K) = 72KB  (2 CTAs/SM — do NOT exceed)
#define STAGES 3
#define STAGE_BYTES 24576
#define SMEM_BYTES (STAGES * STAGE_BYTES)

// ---------------- MMA for one K=64 stage: warp tile 32x32 (8 warps over 128x64) ----------------
__device__ __forceinline__ void stage_mma(uint32_t sbase, uint32_t Aoff, uint32_t Boff,
                                          int am_base, int bn_base, int lane,
                                          float (&acc)[2][4][4])
{
    const int arow = ((lane >> 3) & 1) * 8 + (lane & 7);
    const int akb  = ((lane >> 4) & 1) * 16;
    const int brow = ((lane >> 4) & 1) * 8 + (lane & 7);
    const int bkb  = ((lane >> 3) & 1) * 16;
#pragma unroll
    for (int kk = 0; kk < 64; kk += 16) {
        uint32_t a0[4], a1[4], b0[4], b1[4];
        ldm4(a0, sbase + Aoff + SW128((am_base + arow) * 128 + kk * 2 + akb));
        ldm4(a1, sbase + Aoff + SW128((am_base + 16 + arow) * 128 + kk * 2 + akb));
        ldm4(b0, sbase + Boff + SW128((bn_base + brow) * 128 + kk * 2 + bkb));
        ldm4(b1, sbase + Boff + SW128((bn_base + 16 + brow) * 128 + kk * 2 + bkb));
        mma16816(acc[0][0], a0, b0[0], b0[1]);
        mma16816(acc[0][1], a0, b0[2], b0[3]);
        mma16816(acc[0][2], a0, b1[0], b1[1]);
        mma16816(acc[0][3], a0, b1[2], b1[3]);
        mma16816(acc[1][0], a1, b0[0], b0[1]);
        mma16816(acc[1][1], a1, b0[2], b0[3]);
        mma16816(acc[1][2], a1, b1[0], b1[1]);
        mma16816(acc[1][3], a1, b1[2], b1[3]);
    }
}

// ---------------- epilogues ----------------
// EPI 0: qkv transposed scatter -> bf16 (via smem). 1: out=e4+e5*acc. 2: gelu(bn)->bf16. 3: e4+e5*bn.
template <int EPI, typename OutT>
__device__ __forceinline__ void epi_frag(float (&acc)[2][4][4], char* smem,
                                         int m0, int n0, int wm, int wn, int lane, int t, int ldo,
                                         const float* __restrict__ e0, const float* __restrict__ e1,
                                         const float* __restrict__ e2, const float* __restrict__ e3,
                                         const float* __restrict__ e4, const float* __restrict__ e5,
                                         OutT* __restrict__ out)
{
    const int rIn = lane >> 2, cpair = (lane & 3) * 2;
    if (EPI == 0) {
        float* smf = (float*)smem;     // [64 n][132 m-pad]
        __syncthreads();
#pragma unroll
        for (int ni = 0; ni < 4; ni++) {
            const int cl = wn * 32 + ni * 8 + cpair;
#pragma unroll
            for (int mi = 0; mi < 2; mi++) {
#pragma unroll
                for (int h = 0; h < 2; h++) {
                    const int rl = wm * 32 + mi * 16 + rIn + h * 8;
                    smf[(cl + 0) * 132 + rl] = acc[mi][ni][2 * h + 0];
                    smf[(cl + 1) * 132 + rl] = acc[mi][ni][2 * h + 1];
                }
            }
        }
        __syncthreads();
        const int b = m0 / N_;
        const int nrow0 = (m0 - b * N_);
        const int rown = t & 63, seg = t >> 6;
        const int rr = n0 + rown;
        const int s = rr / C_, cc = rr - s * C_;
        bf16* dst = (bf16*)out + ((size_t)(s * B_ + b) * C_ + cc) * (size_t)N_ + nrow0 + seg * 32;
        const float* src = smf + rown * 132 + seg * 32;
#pragma unroll
        for (int i = 0; i < 8; i++) {
            float4 v = *(const float4*)(src + i * 4);
            __nv_bfloat162 p0 = __floats2bfloat162_rn(v.x, v.y);
            __nv_bfloat162 p1 = __floats2bfloat162_rn(v.z, v.w);
            uint2 u;
            u.x = *(uint32_t*)&p0;
            u.y = *(uint32_t*)&p1;
            *(uint2*)(dst + i * 4) = u;
        }
        return;
    }
#pragma unroll
    for (int ni = 0; ni < 4; ni++) {
        const int col = n0 + wn * 32 + ni * 8 + cpair;
        float s0 = 1.f, s1 = 1.f, bi0 = 0.f, bi1 = 0.f, g0 = 0.f, g1 = 0.f;
        if (EPI == 2 || EPI == 3) {
            s0 = e0[col + 0] * rsqrtf(e3[col + 0] + 1e-5f);
            s1 = e0[col + 1] * rsqrtf(e3[col + 1] + 1e-5f);
            bi0 = e1[col + 0] - e2[col + 0] * s0;
            bi1 = e1[col + 1] - e2[col + 1] * s1;
        }
        if (EPI == 1 || EPI == 3) { g0 = e5[col]; g1 = e5[col + 1]; }
#pragma unroll
        for (int mi = 0; mi < 2; mi++) {
#pragma unroll
            for (int h = 0; h < 2; h++) {
                const int row = m0 + wm * 32 + mi * 16 + rIn + h * 8;
                float a0 = acc[mi][ni][2 * h + 0];
                float a1 = acc[mi][ni][2 * h + 1];
                if (EPI == 2 || EPI == 3) { a0 = a0 * s0 + bi0; a1 = a1 * s1 + bi1; }
                if (EPI == 2) { a0 = gelu_f(a0); a1 = gelu_f(a1); }
                const size_t off = (size_t)row * ldo + col;
                if (EPI == 1 || EPI == 3) {
                    float2 xr = *(const float2*)(e4 + off);
                    a0 = xr.x + g0 * a0; a1 = xr.y + g1 * a1;
                }
                if (sizeof(OutT) == 2) {
                    __nv_bfloat162 p = __floats2bfloat162_rn(a0, a1);
                    *(uint32_t*)((bf16*)out + off) = *(uint32_t*)&p;
                } else {
                    *(float2*)((float*)out + off) = make_float2(a0, a1);
                }
            }
        }
    }
}

// ---------------- dense NT GEMM: D[128x64] = A[128xK] * Bw[64xK]^T, 3-stage cp.async ----------------
template <int EPI, typename OutT>
__global__ void __launch_bounds__(256, 2) tc_gemm(
    const bf16* __restrict__ A, const bf16* __restrict__ Bw, int K, int ldo,
    const float* __restrict__ e0, const float* __restrict__ e1,
    const float* __restrict__ e2, const float* __restrict__ e3,
    const float* __restrict__ e4, const float* __restrict__ e5,
    OutT* __restrict__ out)
{
    extern __shared__ char smem[];
    const int t = threadIdx.x, wid = t >> 5, lane = t & 31;
    const int m0 = blockIdx.x * 128, n0 = blockIdx.y * 64;
    const int wm = wid & 3, wn = wid >> 2;
    const uint32_t sbase = smem_u32(smem);
    const int q = t & 7, r0 = t >> 3;
    const int nc = K >> 6;

    float acc[2][4][4];
#pragma unroll
    for (int i = 0; i < 2; i++)
#pragma unroll
        for (int j = 0; j < 4; j++)
#pragma unroll
            for (int k = 0; k < 4; k++) acc[i][j][k] = 0.f;

    const char* Abase = (const char*)(A + (size_t)m0 * K);
    const char* Bbase = (const char*)(Bw + (size_t)n0 * K);
    const size_t rs = (size_t)K * 2;
    uint32_t sw[4];
#pragma unroll
    for (int it = 0; it < 4; it++) sw[it] = SW128((r0 + it * 32) * 128 + q * 16);

    auto issue = [&](int c) {
        const uint32_t so = sbase + (uint32_t)(c % STAGES) * STAGE_BYTES;
        const size_t ko = (size_t)c * 128 + q * 16;
#pragma unroll
        for (int it = 0; it < 4; it++)
            cpa16(so + sw[it], Abase + (size_t)(r0 + it * 32) * rs + ko);
#pragma unroll
        for (int it = 0; it < 2; it++)
            cpa16(so + 16384 + sw[it], Bbase + (size_t)(r0 + it * 32) * rs + ko);
        CP_COMMIT();
    };

    for (int s = 0; s < STAGES - 1 && s < nc; s++) issue(s);
    for (int c = 0; c < nc; c++) {
        if (c + STAGES - 1 < nc) {
            asm volatile("cp.async.wait_group %0;" :: "n"(STAGES - 2) : "memory");
        } else {
            asm volatile("cp.async.wait_group 0;" ::: "memory");
        }
        __syncthreads();
        const uint32_t so = (uint32_t)(c % STAGES) * STAGE_BYTES;
        stage_mma(sbase, so, so + 16384, wm * 32, wn * 32, lane, acc);
        if (c + STAGES - 1 < nc) issue(c + STAGES - 1);
    }
    epi_frag<EPI, OutT>(acc, smem, m0, n0, wm, wn, lane, t, ldo, e0, e1, e2, e3, e4, e5, out);
}

// ---------------- 3x3 conv as 9-tap K-accumulated GEMM, 3-stage cp.async ----------------
template <int EPI, typename OutT>
__global__ void __launch_bounds__(256, 2) tc_conv(
    const bf16* __restrict__ A, const bf16* __restrict__ Wt,
    const float* __restrict__ e0, const float* __restrict__ e1,
    const float* __restrict__ e2, const float* __restrict__ e3,
    const float* __restrict__ e4, const float* __restrict__ e5,
    OutT* __restrict__ out)
{
    extern __shared__ char smem[];
    const int t = threadIdx.x, wid = t >> 5, lane = t & 31;
    const int m0 = blockIdx.x * 128, n0 = blockIdx.y * 64;
    const int wm = wid & 3, wn = wid >> 2;
    const uint32_t sbase = smem_u32(smem);
    const int q = t & 7, r0 = t >> 3;

    const int m0p = m0 % N_;
    int hh[4], ww[4];
#pragma unroll
    for (int it = 0; it < 4; it++) {
        int p = m0p + r0 + it * 32;
        hh[it] = p / WW_;
        ww[it] = p - hh[it] * WW_;
    }
    uint32_t sw[4];
#pragma unroll
    for (int it = 0; it < 4; it++) sw[it] = SW128((r0 + it * 32) * 128 + q * 16);

    float acc[2][4][4];
#pragma unroll
    for (int i = 0; i < 2; i++)
#pragma unroll
        for (int j = 0; j < 4; j++)
#pragma unroll
            for (int k = 0; k < 4; k++) acc[i][j][k] = 0.f;

    auto issue = [&](int c) {
        const int tap = c / 6, kc = c - tap * 6;
        const int dy = tap / 3 - 1, dx = tap % 3 - 1;
        const uint32_t so = sbase + (uint32_t)(c % STAGES) * STAGE_BYTES;
        const bf16* Atap = A + (size_t)(m0 + dy * WW_ + dx) * C_ + kc * 64;
        const bf16* Wtap = Wt + (size_t)tap * C_ * C_ + (size_t)n0 * C_ + kc * 64;
#pragma unroll
        for (int it = 0; it < 4; it++) {
            bool ok = ((unsigned)(hh[it] + dy) < (unsigned)HH_) &&
                      ((unsigned)(ww[it] + dx) < (unsigned)WW_);
            cpa16z(so + sw[it], (const char*)(Atap + (size_t)(r0 + it * 32) * C_) + q * 16, ok);
        }
#pragma unroll
        for (int it = 0; it < 2; it++)
            cpa16(so + 16384 + sw[it], (const char*)(Wtap + (size_t)(r0 + it * 32) * C_) + q * 16);
        CP_COMMIT();
    };

    const int nc = 54;
    for (int s = 0; s < STAGES - 1; s++) issue(s);
    for (int c = 0; c < nc; c++) {
        if (c + STAGES - 1 < nc) {
            asm volatile("cp.async.wait_group %0;" :: "n"(STAGES - 2) : "memory");
        } else {
            asm volatile("cp.async.wait_group 0;" ::: "memory");
        }
        __syncthreads();
        const uint32_t so = (uint32_t)(c % STAGES) * STAGE_BYTES;
        stage_mma(sbase, so, so + 16384, wm * 32, wn * 32, lane, acc);
        if (c + STAGES - 1 < nc) issue(c + STAGES - 1);
    }
    epi_frag<EPI, OutT>(acc, smem, m0, n0, wm, wn, lane, t, C_, e0, e1, e2, e3, e4, e5, out);
}

// ---------------- LayerNorm -> bf16 ----------------
__global__ void ln_kernel(const float* __restrict__ in, const float* __restrict__ g,
                          const float* __restrict__ b, bf16* __restrict__ outp)
{
    const int r = blockIdx.x;
    const int t = threadIdx.x;
    const float* row = in + (size_t)r * C_;
    float v0 = row[t], v1 = row[t + 128], v2 = row[t + 256];
    float s = v0 + v1 + v2;
    float ss = v0 * v0 + v1 * v1 + v2 * v2;
    for (int o = 16; o; o >>= 1) {
        s  += __shfl_down_sync(0xffffffffu, s,  o);
        ss += __shfl_down_sync(0xffffffffu, ss, o);
    }
    __shared__ float sh[8];
    if ((t & 31) == 0) { sh[t >> 5] = s; sh[4 + (t >> 5)] = ss; }
    __syncthreads();
    if (t == 0) {
        float S  = sh[0] + sh[1] + sh[2] + sh[3];
        float SS = sh[4] + sh[5] + sh[6] + sh[7];
        float mean = S * (1.0f / C_);
        float var  = SS * (1.0f / C_) - mean * mean;
        sh[0] = mean;
        sh[1] = rsqrtf(var + 1e-5f);
    }
    __syncthreads();
    float mean = sh[0], rstd = sh[1];
    bf16* orow = outp + (size_t)r * C_;
    orow[t]       = __float2bfloat16_rn((v0 - mean) * rstd * g[t]       + b[t]);
    orow[t + 128] = __float2bfloat16_rn((v1 - mean) * rstd * g[t + 128] + b[t + 128]);
    orow[t + 256] = __float2bfloat16_rn((v2 - mean) * rstd * g[t + 256] + b[t + 256]);
}

// ---------------- conversions ----------------
__global__ void f2bf(const float* __restrict__ in, bf16* __restrict__ outp, int n)
{
    int i = blockIdx.x * 256 + threadIdx.x;
    if (i < n) outp[i] = __float2bfloat16_rn(in[i]);
}
__global__ void wtrans_bf(const float* __restrict__ w, bf16* __restrict__ wt)
{
    int i = blockIdx.x * 256 + threadIdx.x;
    if (i >= 9 * C_ * C_) return;
    int tap = i / (C_ * C_);
    int rem = i - tap * (C_ * C_);
    int o = rem / C_, ci = rem - o * C_;
    wt[i] = __float2bfloat16_rn(w[(size_t)(o * C_ + ci) * 9 + tap]);
}

// ---------------- fused q/k norm + S + softmax: one block per (b,h) ----------------
__global__ void attn_qk(const float* __restrict__ temp)
{
    const int bh = blockIdx.x;
    const int b = bh >> 3, h = bh & 7;
    __shared__ float qs[DD_ * 65];
    __shared__ float ks[DD_ * 65];
    __shared__ float qss_s[DD_];
    __shared__ float kss_s[DD_];
    const int t = threadIdx.x;
    const bf16* qbase = g_qkvT + ((size_t)(b)      * C_ + h * DD_) * N_;
    const bf16* kbase = g_qkvT + ((size_t)(B_ + b) * C_ + h * DD_) * N_;
    float acc[3][3] = {};
    float qss[3] = {0.f, 0.f, 0.f}, kss[3] = {0.f, 0.f, 0.f};
    const int ty = t >> 4, tx = t & 15;
    const int d0 = ty * 3, e0i = tx * 3;
    for (int n0 = 0; n0 < N_; n0 += 64) {
        __syncthreads();
        for (int idx = t; idx < DD_ * 32; idx += 256) {
            int d = idx >> 5, nn2 = (idx & 31) * 2;
            float2 qf = __bfloat1622float2(*(const __nv_bfloat162*)(qbase + (size_t)d * N_ + n0 + nn2));
            float2 kf = __bfloat1622float2(*(const __nv_bfloat162*)(kbase + (size_t)d * N_ + n0 + nn2));
            qs[d * 65 + nn2] = qf.x; qs[d * 65 + nn2 + 1] = qf.y;
            ks[d * 65 + nn2] = kf.x; ks[d * 65 + nn2 + 1] = kf.y;
        }
        __syncthreads();
#pragma unroll 4
        for (int nn = 0; nn < 64; nn++) {
            float q0 = qs[d0 * 65 + nn], q1 = qs[(d0 + 1) * 65 + nn], q2 = qs[(d0 + 2) * 65 + nn];
            float k0 = ks[e0i * 65 + nn], k1 = ks[(e0i + 1) * 65 + nn], k2 = ks[(e0i + 2) * 65 + nn];
            acc[0][0] += q0 * k0; acc[0][1] += q0 * k1; acc[0][2] += q0 * k2;
            acc[1][0] += q1 * k0; acc[1][1] += q1 * k1; acc[1][2] += q1 * k2;
            acc[2][0] += q2 * k0; acc[2][1] += q2 * k1; acc[2][2] += q2 * k2;
            if (tx == 0) { qss[0] += q0 * q0; qss[1] += q1 * q1; qss[2] += q2 * q2; }
            if (ty == 0) { kss[0] += k0 * k0; kss[1] += k1 * k1; kss[2] += k2 * k2; }
        }
    }
    if (tx == 0) {
#pragma unroll
        for (int i = 0; i < 3; i++) qss_s[d0 + i] = qss[i];
    }
    if (ty == 0) {
#pragma unroll
        for (int j = 0; j < 3; j++) kss_s[e0i + j] = kss[j];
    }
    __syncthreads();
    const float tp = temp[h];
    float rq[3], rk[3];
#pragma unroll
    for (int i = 0; i < 3; i++) rq[i] = 1.0f / fmaxf(sqrtf(qss_s[d0 + i]), 1e-12f);
#pragma unroll
    for (int j = 0; j < 3; j++) rk[j] = 1.0f / fmaxf(sqrtf(kss_s[e0i + j]), 1e-12f);
    float* S = qs;    // reuse, 48*48 floats
    __syncthreads();
#pragma unroll
    for (int i = 0; i < 3; i++)
#pragma unroll
        for (int j = 0; j < 3; j++)
            S[(d0 + i) * DD_ + e0i + j] = acc[i][j] * rq[i] * rk[j] * tp;
    __syncthreads();
    if (t < DD_) {
        float mx = -1e30f;
#pragma unroll
        for (int j = 0; j < DD_; j++) mx = fmaxf(mx, S[t * DD_ + j]);
        float sum = 0.f;
#pragma unroll
        for (int j = 0; j < DD_; j++) { float e = expf(S[t * DD_ + j] - mx); S[t * DD_ + j] = e; sum += e; }
        float r = 1.0f / sum;
        float* dst = g_attn + (size_t)bh * DD_ * DD_ + t * DD_;
#pragma unroll
        for (int j = 0; j < DD_; j++) dst[j] = S[t * DD_ + j] * r;
    }
}

__global__ void attn_v()
{
    const int nt = blockIdx.x;
    const int bh = blockIdx.y;
    const int b = bh >> 3, h = bh & 7;
    __shared__ float P[DD_ * DD_];
    __shared__ float vs[DD_ * 132];
    const int t = threadIdx.x;
    for (int idx = t; idx < DD_ * DD_; idx += 256) P[idx] = g_attn[(size_t)bh * DD_ * DD_ + idx];
    const bf16* vbase = g_qkvT + ((size_t)(2 * B_ + b) * C_ + h * DD_) * N_ + nt * 128;
    for (int idx = t; idx < DD_ * 64; idx += 256) {
        int e = idx >> 6, nn2 = (idx & 63) * 2;
        float2 vf = __bfloat1622float2(*(const __nv_bfloat162*)(vbase + (size_t)e * N_ + nn2));
        vs[e * 132 + nn2] = vf.x;
        vs[e * 132 + nn2 + 1] = vf.y;
    }
    __syncthreads();
    const int ng = t & 31, dg = t >> 5;
    const int n = ng * 4, dd0 = dg * 6;
    float acc[6][4] = {};
#pragma unroll 4
    for (int e = 0; e < DD_; e++) {
        float4 v4 = *(const float4*)&vs[e * 132 + n];
#pragma unroll
        for (int i = 0; i < 6; i++) {
            float pv = P[(dd0 + i) * DD_ + e];
            acc[i][0] += pv * v4.x; acc[i][1] += pv * v4.y;
            acc[i][2] += pv * v4.z; acc[i][3] += pv * v4.w;
        }
    }
    size_t mbase = ((size_t)b * N_ + nt * 128 + n) * C_ + h * DD_ + dd0;
#pragma unroll
    for (int i = 0; i < 6; i++)
#pragma unroll
        for (int jj = 0; jj < 4; jj++)
            g_oncb[mbase + i + (size_t)jj * C_] = __float2bfloat16_rn(acc[i][jj]);
}

__global__ void tail_kernel(float* o, const int* pH, const int* pW, int extra)
{
    int i = threadIdx.x;
    if (i < extra) {
        float v = 0.f;
        if (i == 0) v = (float)(*pH);
        if (i == 1) v = (float)(*pW);
        o[(size_t)ROWS_ * C_ + i] = v;
    }
}

extern "C" void kernel_launch(void* const* d_in, const int* in_sizes, int n_in,
                              void* d_out, int out_size)
{
    const float* x      = (const float*)d_in[0];
    const float* ln1_g  = (const float*)d_in[1];
    const float* ln1_b  = (const float*)d_in[2];
    const float* w_qkv  = (const float*)d_in[3];
    const float* temp   = (const float*)d_in[4];
    const float* w_proj = (const float*)d_in[5];
    const float* gamma1 = (const float*)d_in[6];
    const float* ln2_g  = (const float*)d_in[7];
    const float* ln2_b  = (const float*)d_in[8];
    const float* mlp_w1 = (const float*)d_in[9];
    const float* bn1_g  = (const float*)d_in[10];
    const float* bn1_b  = (const float*)d_in[11];
    const float* bn1_m  = (const float*)d_in[12];
    const float* bn1_v  = (const float*)d_in[13];
    const float* mlp_w2 = (const float*)d_in[14];
    const float* bn2_g  = (const float*)d_in[15];
    const float* bn2_b  = (const float*)d_in[16];
    const float* bn2_m  = (const float*)d_in[17];
    const float* bn2_v  = (const float*)d_in[18];
    const float* gamma2 = (const float*)d_in[19];
    const float* ln3_g  = (const float*)d_in[20];
    const float* ln3_b  = (const float*)d_in[21];
    const float* pconv1 = (const float*)d_in[22];
    const float* pbn_g  = (const float*)d_in[23];
    const float* pbn_b  = (const float*)d_in[24];
    const float* pbn_m  = (const float*)d_in[25];
    const float* pbn_v  = (const float*)d_in[26];
    const float* pconv2 = (const float*)d_in[27];
    const float* gamma3 = (const float*)d_in[28];
    const int*   pH     = (const int*)d_in[29];
    const int*   pW     = (const int*)d_in[30];
    float* dout = (float*)d_out;

    bf16 *xnb, *qkvT, *oncb, *hidb, *c1b, *wqkvb, *wprojb, *w1b, *w2b, *wt1b, *wt2b;
    float *x1, *x2;
    cudaGetSymbolAddress((void**)&xnb,    g_xnb);
    cudaGetSymbolAddress((void**)&qkvT,   g_qkvT);
    cudaGetSymbolAddress((void**)&oncb,   g_oncb);
    cudaGetSymbolAddress((void**)&x1,     g_x1);
    cudaGetSymbolAddress((void**)&hidb,   g_hidb);
    cudaGetSymbolAddress((void**)&x2,     g_x2);
    cudaGetSymbolAddress((void**)&c1b,    g_c1b);
    cudaGetSymbolAddress((void**)&wqkvb,  g_wqkvb);
    cudaGetSymbolAddress((void**)&wprojb, g_wprojb);
    cudaGetSymbolAddress((void**)&w1b,    g_w1b);
    cudaGetSymbolAddress((void**)&w2b,    g_w2b);
    cudaGetSymbolAddress((void**)&wt1b,   g_wt1b);
    cudaGetSymbolAddress((void**)&wt2b,   g_wt2b);

    cudaFuncSetAttribute((const void*)tc_gemm<0, bf16>,  cudaFuncAttributeMaxDynamicSharedMemorySize, SMEM_BYTES);
    cudaFuncSetAttribute((const void*)tc_gemm<1, float>, cudaFuncAttributeMaxDynamicSharedMemorySize, SMEM_BYTES);
    cudaFuncSetAttribute((const void*)tc_gemm<2, bf16>,  cudaFuncAttributeMaxDynamicSharedMemorySize, SMEM_BYTES);
    cudaFuncSetAttribute((const void*)tc_gemm<3, float>, cudaFuncAttributeMaxDynamicSharedMemorySize, SMEM_BYTES);
    cudaFuncSetAttribute((const void*)tc_conv<2, bf16>,  cudaFuncAttributeMaxDynamicSharedMemorySize, SMEM_BYTES);
    cudaFuncSetAttribute((const void*)tc_conv<1, float>, cudaFuncAttributeMaxDynamicSharedMemorySize, SMEM_BYTES);

    const float* np = nullptr;

    // weight conversions
    f2bf<<<(3 * C_ * C_ + 255) / 256, 256>>>(w_qkv, wqkvb, 3 * C_ * C_);
    f2bf<<<(C_ * C_ + 255) / 256, 256>>>(w_proj, wprojb, C_ * C_);
    f2bf<<<(C2_ * C_ + 255) / 256, 256>>>(mlp_w1, w1b, C2_ * C_);
    f2bf<<<(C_ * C2_ + 255) / 256, 256>>>(mlp_w2, w2b, C_ * C2_);
    wtrans_bf<<<(9 * C_ * C_ + 255) / 256, 256>>>(pconv1, wt1b);
    wtrans_bf<<<(9 * C_ * C_ + 255) / 256, 256>>>(pconv2, wt2b);

    // --- attention block ---
    ln_kernel<<<ROWS_, 128>>>(x, ln1_g, ln1_b, xnb);
    tc_gemm<0, bf16><<<dim3(288, 18), 256, SMEM_BYTES>>>(xnb, wqkvb, C_, 0, np, np, np, np, np, np, qkvT);
    attn_qk<<<B_ * NH_, 256>>>(temp);
    attn_v<<<dim3(18, B_ * NH_), 256>>>();
    tc_gemm<1, float><<<dim3(288, 6), 256, SMEM_BYTES>>>(oncb, wprojb, C_, C_, np, np, np, np, x, gamma1, x1);

    // --- ConvMlp block ---
    ln_kernel<<<ROWS_, 128>>>(x1, ln2_g, ln2_b, xnb);
    tc_gemm<2, bf16><<<dim3(288, 12), 256, SMEM_BYTES>>>(xnb, w1b, C_, C2_, bn1_g, bn1_b, bn1_m, bn1_v, np, np, hidb);
    tc_gemm<3, float><<<dim3(288, 6), 256, SMEM_BYTES>>>(hidb, w2b, C2_, C_, bn2_g, bn2_b, bn2_m, bn2_v, x1, gamma2, x2);

    // --- projection block (3x3 convs) ---
    ln_kernel<<<ROWS_, 128>>>(x2, ln3_g, ln3_b, xnb);
    tc_conv<2, bf16><<<dim3(288, 6), 256, SMEM_BYTES>>>(xnb, wt1b, pbn_g, pbn_b, pbn_m, pbn_v, np, np, c1b);
    tc_conv<1, float><<<dim3(288, 6), 256, SMEM_BYTES>>>(c1b, wt2b, np, np, np, np, x2, gamma3, dout);

    int extra = out_size - (int)((size_t)ROWS_ * C_);
    if (extra > 0) tail_kernel<<<1, 32>>>(dout, pH, pW, extra);
}